// round 1
// baseline (speedup 1.0000x reference)
#include <cuda_runtime.h>
#include <cstdint>

// ---------------- problem constants ----------------
#define B      128
#define D      768
#define POOL   100
#define LG     6
#define LE     6
#define GLEN   5
#define ELEN   20
#define H      12
#define HD     64
#define TOPK   5

// g_out: [LG,2,B,H,GLEN,HD]  floats
#define G_FLOATS   (LG*2*B*H*GLEN*HD)          // 5,898,240
#define G_VEC4     (G_FLOATS/4)                // 1,474,560
// e_out: [LE,2,B,H,TOPK*ELEN,HD] floats
#define E_FLOATS   (LE*2*B*H*(TOPK*ELEN)*HD)   // 117,964,800
#define E_VEC4     (E_FLOATS/4)                // 29,491,200

// scratch for selected indices (no cudaMalloc allowed)
__device__ int d_idx[B * TOPK];

// ---------------------------------------------------------------------------
// Kernel 1: cosine-sim + top-5 selection. One block per query row (128 blocks,
// 128 threads). Tie-break = lowest index (first strict max), matching
// jax.lax.top_k on distinct values.
// ---------------------------------------------------------------------------
__global__ void select_topk_kernel(const float* __restrict__ query,
                                   const float* __restrict__ keys) {
    const int b = blockIdx.x;
    const int t = threadIdx.x;
    __shared__ float sims[POOL];
    __shared__ float red[128];

    const float* qr = query + (size_t)b * D;

    // |q_b|
    float s = 0.f;
    for (int i = t; i < D; i += 128) { float v = qr[i]; s += v * v; }
    red[t] = s;
    __syncthreads();
    for (int o = 64; o > 0; o >>= 1) {
        if (t < o) red[t] += red[t + o];
        __syncthreads();
    }
    float qn = fmaxf(sqrtf(red[0]), 1e-12f);

    // each thread < POOL computes one key's dot + norm
    if (t < POOL) {
        const float* kr = keys + (size_t)t * D;
        float dot = 0.f, kk = 0.f;
        #pragma unroll 8
        for (int i = 0; i < D; i++) {
            float kv = kr[i];
            dot = fmaf(qr[i], kv, dot);
            kk  = fmaf(kv, kv, kk);
        }
        float kn = fmaxf(sqrtf(kk), 1e-12f);
        sims[t] = dot / (qn * kn);
    }
    __syncthreads();

    if (t == 0) {
        #pragma unroll
        for (int k = 0; k < TOPK; k++) {
            float best = -3.0e38f; int bi = 0;
            for (int p = 0; p < POOL; p++) {
                if (sims[p] > best) { best = sims[p]; bi = p; }
            }
            d_idx[b * TOPK + k] = bi;
            sims[bi] = -3.0e38f;
        }
    }
}

// ---------------------------------------------------------------------------
// Kernel 2: g_out writer.
// out[l,d,b,h,g,c] = g_prompt[l,d,g,h,c]   (broadcast over b, swap g<->h)
// Linear out float4 index -> coordinates, fully coalesced streaming store.
// ---------------------------------------------------------------------------
__global__ void g_write_kernel(const float4* __restrict__ g4,
                               float4* __restrict__ out4) {
    int tid = blockIdx.x * blockDim.x + threadIdx.x;
    if (tid >= G_VEC4) return;
    int v  = tid;
    int c4 = v & 15;  v >>= 4;     // hd/4 = 16
    int gl = v % GLEN; v /= GLEN;
    int h  = v % H;    v /= H;
    v >>= 7;                        // drop b (128)
    int ld = v;                     // l*2+d in [0,12)
    // src float4 layout: [LG*2, GLEN, H, 16]
    float4 val = __ldg(&g4[((ld * GLEN + gl) * H + h) * 16 + c4]);
    __stcs(&out4[tid], val);
}

// ---------------------------------------------------------------------------
// Kernel 3: e_out writer (the 472 MB gather).
// out[l,d,b,h,m,c] = pool[idx[b][m/ELEN], l, d, m%ELEN, h, c]
// Output-linear -> coalesced streaming stores; pool reads hit L2 (74 MB pool,
// protected from write-stream eviction by __stcs stores).
// ---------------------------------------------------------------------------
__global__ void e_gather_kernel(const float4* __restrict__ pool4,
                                float4* __restrict__ out4) {
    long long tid = (long long)blockIdx.x * blockDim.x + threadIdx.x;
    if (tid >= (long long)E_VEC4) return;
    long long v = tid;
    int c4 = (int)(v & 15); v >>= 4;          // hd/4
    int m  = (int)(v % (TOPK * ELEN)); v /= (TOPK * ELEN);  // 100
    int h  = (int)(v % H); v /= H;
    int b  = (int)(v & 127); v >>= 7;
    int ld = (int)v;                           // l*2+d in [0,12)
    int k  = m / ELEN;
    int e  = m - k * ELEN;
    int p  = d_idx[b * TOPK + k];
    // pool float4 layout: [POOL, LG*2(=12), ELEN, H, 16]
    float4 val = __ldg(&pool4[(((((long long)p * 12 + ld) * ELEN + e) * H + h) * 16) + c4]);
    __stcs(&out4[(long long)G_VEC4 + tid], val);
}

// ---------------------------------------------------------------------------
extern "C" void kernel_launch(void* const* d_in, const int* in_sizes, int n_in,
                              void* d_out, int out_size) {
    const float* query = (const float*)d_in[0];
    const float* gprm  = (const float*)d_in[1];
    const float* pool  = (const float*)d_in[2];
    const float* keys  = (const float*)d_in[3];
    float* out = (float*)d_out;

    // 1. top-k selection
    select_topk_kernel<<<B, 128>>>(query, keys);

    // 2. g broadcast write
    {
        int threads = 256;
        int blocks = (G_VEC4 + threads - 1) / threads;
        g_write_kernel<<<blocks, threads>>>((const float4*)gprm, (float4*)out);
    }

    // 3. e gather write (depends on d_idx; same stream => ordered)
    {
        int threads = 256;
        long long blocks = ((long long)E_VEC4 + 255) / 256;
        e_gather_kernel<<<(int)blocks, 256>>>((const float4*)pool, (float4*)out);
    }
}

// round 2
// speedup vs baseline: 1.2139x; 1.2139x over previous
#include <cuda_runtime.h>
#include <cstdint>

// ---------------- problem constants ----------------
#define B      128
#define D      768
#define POOL   100
#define LG     6
#define LE     6
#define GLEN   5
#define ELEN   20
#define H      12
#define HD     64
#define TOPK   5

// g_out: [LG,2,B,H,GLEN,HD]  floats
#define G_FLOATS   (LG*2*B*H*GLEN*HD)          // 5,898,240
#define G_VEC4     (G_FLOATS/4)                // 1,474,560
// e_out: [LE,2,B,H,TOPK*ELEN,HD] floats
#define E_FLOATS   (LE*2*B*H*(TOPK*ELEN)*HD)   // 117,964,800
#define E_VEC4     (E_FLOATS/4)                // 29,491,200
#define TOTAL_VEC4 (G_VEC4 + E_VEC4)

// scratch for selected indices (no cudaMalloc allowed)
__device__ int d_idx[B * TOPK];

// ---------------------------------------------------------------------------
// Kernel 1: cosine-sim + top-5 selection.
// One block per query row (128 blocks, 256 threads = 8 warps).
// Each WARP computes one full dot product with lane-strided (coalesced)
// loads + shfl reduction; warps stride over the 100 pool entries.
// Tie-break = lowest index (first strict max), matching jax.lax.top_k.
// ---------------------------------------------------------------------------
__global__ void select_topk_kernel(const float* __restrict__ query,
                                   const float* __restrict__ keys) {
    const int b    = blockIdx.x;
    const int t    = threadIdx.x;
    const int warp = t >> 5;
    const int lane = t & 31;

    __shared__ float sims[POOL];
    __shared__ float red[256];
    __shared__ float qn_sh;

    const float* qr = query + (size_t)b * D;

    // ---- |q_b| : block-wide reduction ----
    float s = 0.f;
    for (int i = t; i < D; i += 256) { float v = qr[i]; s = fmaf(v, v, s); }
    red[t] = s;
    __syncthreads();
    for (int o = 128; o > 0; o >>= 1) {
        if (t < o) red[t] += red[t + o];
        __syncthreads();
    }
    if (t == 0) qn_sh = fmaxf(sqrtf(red[0]), 1e-12f);
    __syncthreads();
    const float qn = qn_sh;

    // ---- per-warp dot products over pool entries ----
    for (int p = warp; p < POOL; p += 8) {
        const float* kr = keys + (size_t)p * D;
        float dot = 0.f, kk = 0.f;
        #pragma unroll
        for (int i = lane; i < D; i += 32) {   // 24 iters
            float kv = kr[i];
            float qv = qr[i];
            dot = fmaf(qv, kv, dot);
            kk  = fmaf(kv, kv, kk);
        }
        #pragma unroll
        for (int o = 16; o > 0; o >>= 1) {
            dot += __shfl_down_sync(0xFFFFFFFFu, dot, o);
            kk  += __shfl_down_sync(0xFFFFFFFFu, kk,  o);
        }
        if (lane == 0) {
            float kn = fmaxf(sqrtf(kk), 1e-12f);
            sims[p] = dot / (qn * kn);
        }
    }
    __syncthreads();

    // ---- serial top-5 (500 iterations, trivial) ----
    if (t == 0) {
        #pragma unroll
        for (int k = 0; k < TOPK; k++) {
            float best = -3.0e38f; int bi = 0;
            for (int p = 0; p < POOL; p++) {
                if (sims[p] > best) { best = sims[p]; bi = p; }
            }
            d_idx[b * TOPK + k] = bi;
            sims[bi] = -3.0e38f;
        }
    }
}

// ---------------------------------------------------------------------------
// Kernel 2: fused output writer (g broadcast + e gather), output-linear,
// fully coalesced float4 streaming stores.
//   g region: out[l,d,b,h,g,c] = g_prompt[l,d,g,h,c]
//   e region: out[l,d,b,h,m,c] = pool[idx[b][m/ELEN], l, d, m%ELEN, h, c]
// ---------------------------------------------------------------------------
__global__ void write_out_kernel(const float4* __restrict__ g4,
                                 const float4* __restrict__ pool4,
                                 float4* __restrict__ out4) {
    long long tid = (long long)blockIdx.x * blockDim.x + threadIdx.x;
    if (tid >= (long long)TOTAL_VEC4) return;

    if (tid < (long long)G_VEC4) {
        int v  = (int)tid;
        int c4 = v & 15;  v >>= 4;       // hd/4 = 16
        int gl = v % GLEN; v /= GLEN;
        int h  = v % H;    v /= H;
        v >>= 7;                          // drop b (128)
        int ld = v;                       // l*2+d in [0,12)
        // src float4 layout: [LG*2, GLEN, H, 16]
        float4 val = __ldg(&g4[((ld * GLEN + gl) * H + h) * 16 + c4]);
        __stcs(&out4[tid], val);
    } else {
        long long v = tid - G_VEC4;
        long long otid = tid;
        int c4 = (int)(v & 15); v >>= 4;               // hd/4
        int m  = (int)(v % (TOPK * ELEN)); v /= (TOPK * ELEN);  // 100
        int h  = (int)(v % H); v /= H;
        int b  = (int)(v & 127); v >>= 7;
        int ld = (int)v;                               // l*2+d in [0,12)
        int k  = m / ELEN;
        int e  = m - k * ELEN;
        int p  = d_idx[b * TOPK + k];
        // pool float4 layout: [POOL, LE*2(=12), ELEN, H, 16]
        float4 val = __ldg(&pool4[(((((long long)p * 12 + ld) * ELEN + e) * H + h) * 16) + c4]);
        __stcs(&out4[otid], val);
    }
}

// ---------------------------------------------------------------------------
extern "C" void kernel_launch(void* const* d_in, const int* in_sizes, int n_in,
                              void* d_out, int out_size) {
    const float* query = (const float*)d_in[0];
    const float* gprm  = (const float*)d_in[1];
    const float* pool  = (const float*)d_in[2];
    const float* keys  = (const float*)d_in[3];
    float* out = (float*)d_out;

    // 1. top-k selection (fast: ~3 us)
    select_topk_kernel<<<B, 256>>>(query, keys);

    // 2. fused g + e writer (depends on d_idx; same stream => ordered)
    {
        const int threads = 256;
        long long blocks = ((long long)TOTAL_VEC4 + threads - 1) / threads;
        write_out_kernel<<<(int)blocks, threads>>>((const float4*)gprm,
                                                   (const float4*)pool,
                                                   (float4*)out);
    }
}